// round 1
// baseline (speedup 1.0000x reference)
#include <cuda_runtime.h>
#include <cuda_bf16.h>
#include <cstdint>

// Problem constants
#define BATCH 2
#define SEQ   2048
#define DIM   1024
#define HEADS 16
#define HD    64        // head dim
#define NTOK  (BATCH*SEQ)   // 4096

// Scratch (allocation-free rule: __device__ globals)
__device__ float g_qkv[(size_t)NTOK * 3 * DIM];   // 4096 x 3072
__device__ float g_attn[(size_t)NTOK * DIM];      // 4096 x 1024

// ---------------------------------------------------------------------------
// SGEMM: C[M][N] = A[M][K] * B[N][K]^T   (both operands K-major / row-major)
// 128x128 tile, BK=16, 256 threads, 8x8 per thread.
// ---------------------------------------------------------------------------
#define GBM 128
#define GBN 128
#define GBK 16
#define GLD 132   // padded leading dim for smem (multiple of 4, !=0 mod 32)

__global__ __launch_bounds__(256, 2)
void sgemm_tt(const float* __restrict__ A, const float* __restrict__ Bm,
              float* __restrict__ C, int M, int N, int K)
{
    __shared__ float Ast[GBK][GLD];
    __shared__ float Bst[GBK][GLD];

    const int tid = threadIdx.x;
    const int tx = tid & 15;       // 0..15 -> n
    const int ty = tid >> 4;       // 0..15 -> m
    const int m0 = blockIdx.y * GBM;
    const int n0 = blockIdx.x * GBN;

    float c[8][8];
#pragma unroll
    for (int i = 0; i < 8; i++)
#pragma unroll
        for (int j = 0; j < 8; j++) c[i][j] = 0.f;

    for (int k0 = 0; k0 < K; k0 += GBK) {
#pragma unroll
        for (int r = 0; r < 2; r++) {
            int idx = r * 256 + tid;       // 0..511
            int mm  = idx >> 2;            // 0..127
            int kc  = (idx & 3) << 2;      // 0,4,8,12
            float4 av = *(const float4*)(A  + (size_t)(m0 + mm) * K + k0 + kc);
            Ast[kc + 0][mm] = av.x;
            Ast[kc + 1][mm] = av.y;
            Ast[kc + 2][mm] = av.z;
            Ast[kc + 3][mm] = av.w;
            float4 bv = *(const float4*)(Bm + (size_t)(n0 + mm) * K + k0 + kc);
            Bst[kc + 0][mm] = bv.x;
            Bst[kc + 1][mm] = bv.y;
            Bst[kc + 2][mm] = bv.z;
            Bst[kc + 3][mm] = bv.w;
        }
        __syncthreads();

#pragma unroll
        for (int k = 0; k < GBK; k++) {
            float a[8], b[8];
            *(float4*)(a)     = *(const float4*)(&Ast[k][ty * 8]);
            *(float4*)(a + 4) = *(const float4*)(&Ast[k][ty * 8 + 4]);
            *(float4*)(b)     = *(const float4*)(&Bst[k][tx * 8]);
            *(float4*)(b + 4) = *(const float4*)(&Bst[k][tx * 8 + 4]);
#pragma unroll
            for (int i = 0; i < 8; i++)
#pragma unroll
                for (int j = 0; j < 8; j++)
                    c[i][j] += a[i] * b[j];
        }
        __syncthreads();
    }

#pragma unroll
    for (int i = 0; i < 8; i++) {
        int gm = m0 + ty * 8 + i;
#pragma unroll
        for (int j = 0; j < 8; j += 4) {
            float4 cv = make_float4(c[i][j], c[i][j+1], c[i][j+2], c[i][j+3]);
            *(float4*)(&C[(size_t)gm * N + n0 + tx * 8 + j]) = cv;
        }
    }
}

// ---------------------------------------------------------------------------
// Flash attention with ALiBi + causal mask.
// One CTA per (b, h, 64-query tile); 256 threads = 16x16, 4x4 fragment each.
// Q/K in smem d-major (transposed) for float4 microkernel reads.
// P tile aliases K tile. fp32 throughout, online softmax.
// ---------------------------------------------------------------------------
#define LDA 68   // smem leading dim

__global__ __launch_bounds__(256, 2)
void attn_kernel(const float* __restrict__ qkv, float* __restrict__ attn_out)
{
    extern __shared__ float sm[];
    float* Qst  = sm;                 // Qst[d][i]  (64 x LDA)
    float* KPst = sm + HD * LDA;      // Kst[d][j], later aliased as Pst[j][i]
    float* Vs   = sm + 2 * HD * LDA;  // Vs[j][dd]

    const int tid = threadIdx.x;
    const int tx = tid & 15;
    const int ty = tid >> 4;
    const int qt = blockIdx.x;            // 0..31
    const int bh = blockIdx.y;            // 0..31
    const int b  = bh >> 4;
    const int h  = bh & 15;
    const int q0 = qt * 64;

    const float slope = exp2f(-0.5f * (float)(h + 1));
    const float scale = 0.125f;           // 64^-0.5

    const size_t rs = 3 * DIM;             // 3072
    const float* qbase = qkv + (size_t)b * SEQ * rs + h * HD;
    const float* kbase = qbase + DIM;
    const float* vbase = qbase + 2 * DIM;

    // Load Q tile (64x64) transposed + pre-scaled
#pragma unroll
    for (int r = 0; r < 4; r++) {
        int idx = r * 256 + tid;      // 0..1023
        int i   = idx >> 4;           // 0..63
        int dc  = (idx & 15) << 2;    // 0..60
        float4 qv = *(const float4*)(qbase + (size_t)(q0 + i) * rs + dc);
        Qst[(dc + 0) * LDA + i] = qv.x * scale;
        Qst[(dc + 1) * LDA + i] = qv.y * scale;
        Qst[(dc + 2) * LDA + i] = qv.z * scale;
        Qst[(dc + 3) * LDA + i] = qv.w * scale;
    }

    float o[16];
#pragma unroll
    for (int t = 0; t < 16; t++) o[t] = 0.f;
    float m_run[4], l_run[4];
#pragma unroll
    for (int t = 0; t < 4; t++) { m_run[t] = -1e30f; l_run[t] = 0.f; }

    for (int kt = 0; kt <= qt; kt++) {
        const int k0 = kt * 64;
        __syncthreads();   // previous PV done before overwriting Kst/Vs
#pragma unroll
        for (int r = 0; r < 4; r++) {
            int idx = r * 256 + tid;
            int j   = idx >> 4;
            int dc  = (idx & 15) << 2;
            float4 kv = *(const float4*)(kbase + (size_t)(k0 + j) * rs + dc);
            KPst[(dc + 0) * LDA + j] = kv.x;
            KPst[(dc + 1) * LDA + j] = kv.y;
            KPst[(dc + 2) * LDA + j] = kv.z;
            KPst[(dc + 3) * LDA + j] = kv.w;
            float4 vv = *(const float4*)(vbase + (size_t)(k0 + j) * rs + dc);
            *(float4*)(&Vs[j * LDA + dc]) = vv;
        }
        __syncthreads();

        // S = (Q*scale) @ K^T
        float s[4][4];
#pragma unroll
        for (int ii = 0; ii < 4; ii++)
#pragma unroll
            for (int jj = 0; jj < 4; jj++) s[ii][jj] = 0.f;

#pragma unroll 8
        for (int d = 0; d < HD; d++) {
            float4 qa = *(const float4*)(&Qst [d * LDA + ty * 4]);
            float4 kb = *(const float4*)(&KPst[d * LDA + tx * 4]);
            float qq[4] = {qa.x, qa.y, qa.z, qa.w};
            float kk[4] = {kb.x, kb.y, kb.z, kb.w};
#pragma unroll
            for (int ii = 0; ii < 4; ii++)
#pragma unroll
                for (int jj = 0; jj < 4; jj++)
                    s[ii][jj] += qq[ii] * kk[jj];
        }

        // ALiBi + causal
#pragma unroll
        for (int ii = 0; ii < 4; ii++) {
            int gi = q0 + ty * 4 + ii;
#pragma unroll
            for (int jj = 0; jj < 4; jj++) {
                int gj = k0 + tx * 4 + jj;
                s[ii][jj] -= slope * (float)(gj - gi);
                if (gj > gi) s[ii][jj] = -1e30f;
            }
        }

        // Online softmax (rows reduced across the 16 tx lanes)
        float corr[4], rsum[4];
#pragma unroll
        for (int ii = 0; ii < 4; ii++) {
            float v = fmaxf(fmaxf(s[ii][0], s[ii][1]), fmaxf(s[ii][2], s[ii][3]));
            v = fmaxf(v, __shfl_xor_sync(0xffffffff, v, 1));
            v = fmaxf(v, __shfl_xor_sync(0xffffffff, v, 2));
            v = fmaxf(v, __shfl_xor_sync(0xffffffff, v, 4));
            v = fmaxf(v, __shfl_xor_sync(0xffffffff, v, 8));
            float mn = fmaxf(m_run[ii], v);
            corr[ii] = __expf(m_run[ii] - mn);
            m_run[ii] = mn;
            float rsl = 0.f;
#pragma unroll
            for (int jj = 0; jj < 4; jj++) {
                float p = __expf(s[ii][jj] - mn);
                s[ii][jj] = p;
                rsl += p;
            }
            rsl += __shfl_xor_sync(0xffffffff, rsl, 1);
            rsl += __shfl_xor_sync(0xffffffff, rsl, 2);
            rsl += __shfl_xor_sync(0xffffffff, rsl, 4);
            rsl += __shfl_xor_sync(0xffffffff, rsl, 8);
            rsum[ii] = rsl;
        }
#pragma unroll
        for (int ii = 0; ii < 4; ii++) {
            l_run[ii] = l_run[ii] * corr[ii] + rsum[ii];
#pragma unroll
            for (int jj = 0; jj < 4; jj++) o[ii * 4 + jj] *= corr[ii];
        }

        __syncthreads();   // all threads done reading Kst
        // Write P transposed: Pst[j][i] (aliases Kst)
#pragma unroll
        for (int jj = 0; jj < 4; jj++) {
            float4 pv = make_float4(s[0][jj], s[1][jj], s[2][jj], s[3][jj]);
            *(float4*)(&KPst[(tx * 4 + jj) * LDA + ty * 4]) = pv;
        }
        __syncthreads();

        // O += P @ V
#pragma unroll 8
        for (int j = 0; j < 64; j++) {
            float4 pa = *(const float4*)(&KPst[j * LDA + ty * 4]);
            float4 vb = *(const float4*)(&Vs  [j * LDA + tx * 4]);
            float pp[4] = {pa.x, pa.y, pa.z, pa.w};
            float vv[4] = {vb.x, vb.y, vb.z, vb.w};
#pragma unroll
            for (int ii = 0; ii < 4; ii++)
#pragma unroll
                for (int jj = 0; jj < 4; jj++)
                    o[ii * 4 + jj] += pp[ii] * vv[jj];
        }
    }

    // Normalize + write (b, s, h*64+dd) layout — matches reshape in reference
#pragma unroll
    for (int ii = 0; ii < 4; ii++) {
        int gi = q0 + ty * 4 + ii;
        float inv = 1.0f / l_run[ii];
        float4 ov = make_float4(o[ii*4+0]*inv, o[ii*4+1]*inv, o[ii*4+2]*inv, o[ii*4+3]*inv);
        *(float4*)(&attn_out[((size_t)(b * SEQ + gi)) * DIM + h * HD + tx * 4]) = ov;
    }
}

// ---------------------------------------------------------------------------
extern "C" void kernel_launch(void* const* d_in, const int* in_sizes, int n_in,
                              void* d_out, int out_size)
{
    const float* x    = (const float*)d_in[0];   // (2,2048,1024)
    const float* Wqkv = (const float*)d_in[1];   // (3072,1024)
    const float* Wo   = (const float*)d_in[2];   // (1024,1024)
    float* out = (float*)d_out;                  // (2,2048,1024)

    float* qkv = nullptr;
    float* attn = nullptr;
    cudaGetSymbolAddress((void**)&qkv,  g_qkv);
    cudaGetSymbolAddress((void**)&attn, g_attn);

    // 1) qkv = x @ Wqkv^T   (M=4096, N=3072, K=1024)
    {
        dim3 grid(3 * DIM / GBN, NTOK / GBM);
        sgemm_tt<<<grid, 256>>>(x, Wqkv, qkv, NTOK, 3 * DIM, DIM);
    }

    // 2) flash attention with ALiBi + causal
    {
        int smem = 3 * HD * LDA * sizeof(float);   // 52224 B
        cudaFuncSetAttribute(attn_kernel, cudaFuncAttributeMaxDynamicSharedMemorySize, smem);
        dim3 grid(SEQ / 64, BATCH * HEADS);
        attn_kernel<<<grid, 256, smem>>>(qkv, attn);
    }

    // 3) out = attn @ Wo^T   (M=4096, N=1024, K=1024)
    {
        dim3 grid(DIM / GBN, NTOK / GBM);
        sgemm_tt<<<grid, 256>>>(attn, Wo, out, NTOK, DIM, DIM);
    }
}

// round 3
// speedup vs baseline: 1.4566x; 1.4566x over previous
#include <cuda_runtime.h>
#include <cuda_bf16.h>
#include <cstdint>

// Problem constants
#define BATCH 2
#define SEQ   2048
#define DIM   1024
#define HEADS 16
#define HD    64
#define NTOK  (BATCH*SEQ)   // 4096

// ---------------------------------------------------------------------------
// Scratch (__device__ globals; allocation-free rule)
// ---------------------------------------------------------------------------
__device__ float g_qkv [(size_t)NTOK * 3 * DIM];    // 4096 x 3072 fp32
__device__ float g_attn[(size_t)NTOK * DIM];        // 4096 x 1024 fp32
__device__ __nv_bfloat16 g_xhi[(size_t)NTOK * DIM];
__device__ __nv_bfloat16 g_xlo[(size_t)NTOK * DIM];
__device__ __nv_bfloat16 g_wqh[(size_t)3 * DIM * DIM];
__device__ __nv_bfloat16 g_wql[(size_t)3 * DIM * DIM];
__device__ __nv_bfloat16 g_woh[(size_t)DIM * DIM];
__device__ __nv_bfloat16 g_wol[(size_t)DIM * DIM];
__device__ __nv_bfloat16 g_ahi[(size_t)NTOK * DIM];
__device__ __nv_bfloat16 g_alo[(size_t)NTOK * DIM];

// ---------------------------------------------------------------------------
// PTX helpers (all baseline sm_100-safe: cp.async / ldmatrix / mma.sync)
// ---------------------------------------------------------------------------
__device__ __forceinline__ uint32_t smem_u32(const void* p) {
    uint32_t a;
    asm("{ .reg .u64 t; cvta.to.shared.u64 t, %1; cvt.u32.u64 %0, t; }" : "=r"(a) : "l"(p));
    return a;
}
// SW64 swizzle for 64-byte rows: conflict-free ldmatrix on 16B chunks
#define SWZ64(off) ((off) ^ (((off) >> 3) & 0x30))

#define CP_ASYNC16(saddr, gptr) \
    asm volatile("cp.async.cg.shared.global [%0], [%1], 16;\n" :: "r"(saddr), "l"(gptr))
#define CP_COMMIT() asm volatile("cp.async.commit_group;\n" ::: "memory")
#define CP_WAIT(N)  asm volatile("cp.async.wait_group %0;\n" :: "n"(N) : "memory")

#define LDSM_X4(r0, r1, r2, r3, addr) \
    asm volatile("ldmatrix.sync.aligned.m8n8.x4.shared.b16 {%0,%1,%2,%3}, [%4];" \
                 : "=r"(r0), "=r"(r1), "=r"(r2), "=r"(r3) : "r"(addr))

#define MMA16816(c, a, b0, b1) \
    asm volatile("mma.sync.aligned.m16n8k16.row.col.f32.bf16.bf16.f32 " \
                 "{%0,%1,%2,%3}, {%4,%5,%6,%7}, {%8,%9}, {%0,%1,%2,%3};" \
                 : "+f"((c)[0]), "+f"((c)[1]), "+f"((c)[2]), "+f"((c)[3]) \
                 : "r"((a)[0]), "r"((a)[1]), "r"((a)[2]), "r"((a)[3]), \
                   "r"(b0), "r"(b1))

// ---------------------------------------------------------------------------
// split kernel: hi = bf16(x), lo = bf16(x - hi)
// ---------------------------------------------------------------------------
__global__ void split_bf16(const float* __restrict__ src, __nv_bfloat16* __restrict__ hi,
                           __nv_bfloat16* __restrict__ lo, int n4)
{
    int i = blockIdx.x * blockDim.x + threadIdx.x;
    if (i >= n4) return;
    float4 v = ((const float4*)src)[i];
    __nv_bfloat16 h0 = __float2bfloat16(v.x);
    __nv_bfloat16 h1 = __float2bfloat16(v.y);
    __nv_bfloat16 h2 = __float2bfloat16(v.z);
    __nv_bfloat16 h3 = __float2bfloat16(v.w);
    __nv_bfloat16 l0 = __float2bfloat16(v.x - __bfloat162float(h0));
    __nv_bfloat16 l1 = __float2bfloat16(v.y - __bfloat162float(h1));
    __nv_bfloat16 l2 = __float2bfloat16(v.z - __bfloat162float(h2));
    __nv_bfloat16 l3 = __float2bfloat16(v.w - __bfloat162float(h3));
    __nv_bfloat162* hp = (__nv_bfloat162*)(hi + (size_t)i * 4);
    __nv_bfloat162* lp = (__nv_bfloat162*)(lo + (size_t)i * 4);
    hp[0] = __nv_bfloat162(h0, h1);
    hp[1] = __nv_bfloat162(h2, h3);
    lp[0] = __nv_bfloat162(l0, l1);
    lp[1] = __nv_bfloat162(l2, l3);
}

// ---------------------------------------------------------------------------
// 3-term bf16 GEMM via mma.sync:  C[M][N] = A[M][K] * B[N][K]^T  (fp32 out)
//   C = Ahi*Bhi + Alo*Bhi + Ahi*Blo
// CTA tile 128x256, BK=32, 8 warps (64x64 each), 4-stage cp.async pipeline.
// ---------------------------------------------------------------------------
#define BM 128
#define BN 256
#define BK 32
#define NSTAGE 4
#define A_BYTES (BM * BK * 2)            // 8192  per term
#define B_BYTES (BN * BK * 2)            // 16384 per term
#define STAGE_B (2*A_BYTES + 2*B_BYTES)  // 49152
#define GEMM_SMEM (NSTAGE * STAGE_B)     // 196608

__global__ __launch_bounds__(256)
void gemm_bf16x3(const __nv_bfloat16* __restrict__ Ahi, const __nv_bfloat16* __restrict__ Alo,
                 const __nv_bfloat16* __restrict__ Bhi, const __nv_bfloat16* __restrict__ Blo,
                 float* __restrict__ C, int K, int Ntot)
{
    extern __shared__ __align__(1024) char smem[];
    const uint32_t sbase = smem_u32(smem);
    const int tid  = threadIdx.x;
    const int wid  = tid >> 5;
    const int lane = tid & 31;
    const int m0 = blockIdx.y * BM;
    const int n0 = blockIdx.x * BN;

    const int wm = wid & 1;          // 0..1
    const int wn = wid >> 1;         // 0..3
    const int m_off = wm * 64;
    const int n_off = wn * 64;

    const __nv_bfloat16* aS[2] = { Ahi + (size_t)m0 * K, Alo + (size_t)m0 * K };
    const __nv_bfloat16* bS[2] = { Bhi + (size_t)n0 * K, Blo + (size_t)n0 * K };

    const int NIT = K / BK;

    // per-thread load slots: A terms 512 chunks (2 per thread each term),
    // B terms 1024 chunks (4 per thread each term)
    auto load_stage = [&](int sbuf, int k0) {
        uint32_t stg = sbase + sbuf * STAGE_B;
#pragma unroll
        for (int p = 0; p < 2; p++) {
            uint32_t part = stg + p * A_BYTES;
            const __nv_bfloat16* src = aS[p] + k0;
#pragma unroll
            for (int r = 0; r < 2; r++) {
                int idx = r * 256 + tid;          // 0..511
                int row = idx >> 2, c = idx & 3;
                uint32_t soff = SWZ64((uint32_t)(row * 64 + c * 16));
                CP_ASYNC16(part + soff, src + (size_t)row * K + c * 8);
            }
        }
#pragma unroll
        for (int p = 0; p < 2; p++) {
            uint32_t part = stg + 2 * A_BYTES + p * B_BYTES;
            const __nv_bfloat16* src = bS[p] + k0;
#pragma unroll
            for (int r = 0; r < 4; r++) {
                int idx = r * 256 + tid;          // 0..1023
                int row = idx >> 2, c = idx & 3;
                uint32_t soff = SWZ64((uint32_t)(row * 64 + c * 16));
                CP_ASYNC16(part + soff, src + (size_t)row * K + c * 8);
            }
        }
    };

    float c[4][8][4];
#pragma unroll
    for (int i = 0; i < 4; i++)
#pragma unroll
        for (int j = 0; j < 8; j++)
#pragma unroll
            for (int t = 0; t < 4; t++) c[i][j][t] = 0.f;

    // prologue: fill 3 stages
#pragma unroll
    for (int s = 0; s < 3; s++) { load_stage(s, s * BK); CP_COMMIT(); }

    const int lr = lane & 15;
    const int lk = lane >> 4;

    for (int it = 0; it < NIT; it++) {
        CP_WAIT(2);
        __syncthreads();
        if (it + 3 < NIT) { load_stage((it + 3) & 3, (it + 3) * BK); CP_COMMIT(); }

        uint32_t stg  = sbase + (it & 3) * STAGE_B;
        uint32_t aHiB = stg;
        uint32_t aLoB = stg + A_BYTES;
        uint32_t bHiB = stg + 2 * A_BYTES;
        uint32_t bLoB = stg + 2 * A_BYTES + B_BYTES;

#pragma unroll
        for (int ks = 0; ks < 2; ks++) {
            uint32_t ahi[4][4], alo[4][4];
#pragma unroll
            for (int mi = 0; mi < 4; mi++) {
                uint32_t off = (uint32_t)((m_off + mi * 16 + lr) * 64 + ks * 32 + lk * 16);
                uint32_t sw = SWZ64(off);
                LDSM_X4(ahi[mi][0], ahi[mi][1], ahi[mi][2], ahi[mi][3], aHiB + sw);
                LDSM_X4(alo[mi][0], alo[mi][1], alo[mi][2], alo[mi][3], aLoB + sw);
            }
#pragma unroll
            for (int ng = 0; ng < 4; ng++) {
                uint32_t off = (uint32_t)((n_off + ng * 16 + lr) * 64 + ks * 32 + lk * 16);
                uint32_t sw = SWZ64(off);
                uint32_t bh0, bh1, bh2, bh3, bl0, bl1, bl2, bl3;
                LDSM_X4(bh0, bh1, bh2, bh3, bHiB + sw);
                LDSM_X4(bl0, bl1, bl2, bl3, bLoB + sw);
#pragma unroll
                for (int mi = 0; mi < 4; mi++) {
                    MMA16816(c[mi][ng*2+0], ahi[mi], bh0, bh2);
                    MMA16816(c[mi][ng*2+1], ahi[mi], bh1, bh3);
                    MMA16816(c[mi][ng*2+0], alo[mi], bh0, bh2);
                    MMA16816(c[mi][ng*2+1], alo[mi], bh1, bh3);
                    MMA16816(c[mi][ng*2+0], ahi[mi], bl0, bl2);
                    MMA16816(c[mi][ng*2+1], ahi[mi], bl1, bl3);
                }
            }
        }
    }

    // epilogue: fp32 register fragments -> C
    const int cr = lane >> 2;         // 0..7
    const int cc = (lane & 3) * 2;
#pragma unroll
    for (int mi = 0; mi < 4; mi++) {
        int r0 = m0 + m_off + mi * 16 + cr;
#pragma unroll
        for (int j = 0; j < 8; j++) {
            int col = n0 + n_off + j * 8 + cc;
            float2 v0 = make_float2(c[mi][j][0], c[mi][j][1]);
            float2 v1 = make_float2(c[mi][j][2], c[mi][j][3]);
            *(float2*)(C + (size_t)r0 * Ntot + col)       = v0;
            *(float2*)(C + (size_t)(r0 + 8) * Ntot + col) = v1;
        }
    }
}

// ---------------------------------------------------------------------------
// Flash attention with ALiBi + causal mask (fp32 FMA, unchanged from R1 pass)
// ---------------------------------------------------------------------------
#define LDA 68

__global__ __launch_bounds__(256, 2)
void attn_kernel(const float* __restrict__ qkv, float* __restrict__ attn_out)
{
    extern __shared__ float sm[];
    float* Qst  = sm;
    float* KPst = sm + HD * LDA;
    float* Vs   = sm + 2 * HD * LDA;

    const int tid = threadIdx.x;
    const int tx = tid & 15;
    const int ty = tid >> 4;
    const int qt = blockIdx.x;
    const int bh = blockIdx.y;
    const int b  = bh >> 4;
    const int h  = bh & 15;
    const int q0 = qt * 64;

    const float slope = exp2f(-0.5f * (float)(h + 1));
    const float scale = 0.125f;

    const size_t rs = 3 * DIM;
    const float* qbase = qkv + (size_t)b * SEQ * rs + h * HD;
    const float* kbase = qbase + DIM;
    const float* vbase = qbase + 2 * DIM;

#pragma unroll
    for (int r = 0; r < 4; r++) {
        int idx = r * 256 + tid;
        int i   = idx >> 4;
        int dc  = (idx & 15) << 2;
        float4 qv = *(const float4*)(qbase + (size_t)(q0 + i) * rs + dc);
        Qst[(dc + 0) * LDA + i] = qv.x * scale;
        Qst[(dc + 1) * LDA + i] = qv.y * scale;
        Qst[(dc + 2) * LDA + i] = qv.z * scale;
        Qst[(dc + 3) * LDA + i] = qv.w * scale;
    }

    float o[16];
#pragma unroll
    for (int t = 0; t < 16; t++) o[t] = 0.f;
    float m_run[4], l_run[4];
#pragma unroll
    for (int t = 0; t < 4; t++) { m_run[t] = -1e30f; l_run[t] = 0.f; }

    for (int kt = 0; kt <= qt; kt++) {
        const int k0 = kt * 64;
        __syncthreads();
#pragma unroll
        for (int r = 0; r < 4; r++) {
            int idx = r * 256 + tid;
            int j   = idx >> 4;
            int dc  = (idx & 15) << 2;
            float4 kv = *(const float4*)(kbase + (size_t)(k0 + j) * rs + dc);
            KPst[(dc + 0) * LDA + j] = kv.x;
            KPst[(dc + 1) * LDA + j] = kv.y;
            KPst[(dc + 2) * LDA + j] = kv.z;
            KPst[(dc + 3) * LDA + j] = kv.w;
            float4 vv = *(const float4*)(vbase + (size_t)(k0 + j) * rs + dc);
            *(float4*)(&Vs[j * LDA + dc]) = vv;
        }
        __syncthreads();

        float s[4][4];
#pragma unroll
        for (int ii = 0; ii < 4; ii++)
#pragma unroll
            for (int jj = 0; jj < 4; jj++) s[ii][jj] = 0.f;

#pragma unroll 8
        for (int d = 0; d < HD; d++) {
            float4 qa = *(const float4*)(&Qst [d * LDA + ty * 4]);
            float4 kb = *(const float4*)(&KPst[d * LDA + tx * 4]);
            float qq[4] = {qa.x, qa.y, qa.z, qa.w};
            float kk[4] = {kb.x, kb.y, kb.z, kb.w};
#pragma unroll
            for (int ii = 0; ii < 4; ii++)
#pragma unroll
                for (int jj = 0; jj < 4; jj++)
                    s[ii][jj] += qq[ii] * kk[jj];
        }

#pragma unroll
        for (int ii = 0; ii < 4; ii++) {
            int gi = q0 + ty * 4 + ii;
#pragma unroll
            for (int jj = 0; jj < 4; jj++) {
                int gj = k0 + tx * 4 + jj;
                s[ii][jj] -= slope * (float)(gj - gi);
                if (gj > gi) s[ii][jj] = -1e30f;
            }
        }

        float corr[4], rsum[4];
#pragma unroll
        for (int ii = 0; ii < 4; ii++) {
            float v = fmaxf(fmaxf(s[ii][0], s[ii][1]), fmaxf(s[ii][2], s[ii][3]));
            v = fmaxf(v, __shfl_xor_sync(0xffffffff, v, 1));
            v = fmaxf(v, __shfl_xor_sync(0xffffffff, v, 2));
            v = fmaxf(v, __shfl_xor_sync(0xffffffff, v, 4));
            v = fmaxf(v, __shfl_xor_sync(0xffffffff, v, 8));
            float mn = fmaxf(m_run[ii], v);
            corr[ii] = __expf(m_run[ii] - mn);
            m_run[ii] = mn;
            float rsl = 0.f;
#pragma unroll
            for (int jj = 0; jj < 4; jj++) {
                float p = __expf(s[ii][jj] - mn);
                s[ii][jj] = p;
                rsl += p;
            }
            rsl += __shfl_xor_sync(0xffffffff, rsl, 1);
            rsl += __shfl_xor_sync(0xffffffff, rsl, 2);
            rsl += __shfl_xor_sync(0xffffffff, rsl, 4);
            rsl += __shfl_xor_sync(0xffffffff, rsl, 8);
            rsum[ii] = rsl;
        }
#pragma unroll
        for (int ii = 0; ii < 4; ii++) {
            l_run[ii] = l_run[ii] * corr[ii] + rsum[ii];
#pragma unroll
            for (int jj = 0; jj < 4; jj++) o[ii * 4 + jj] *= corr[ii];
        }

        __syncthreads();
#pragma unroll
        for (int jj = 0; jj < 4; jj++) {
            float4 pv = make_float4(s[0][jj], s[1][jj], s[2][jj], s[3][jj]);
            *(float4*)(&KPst[(tx * 4 + jj) * LDA + ty * 4]) = pv;
        }
        __syncthreads();

#pragma unroll 8
        for (int j = 0; j < 64; j++) {
            float4 pa = *(const float4*)(&KPst[j * LDA + ty * 4]);
            float4 vb = *(const float4*)(&Vs  [j * LDA + tx * 4]);
            float pp[4] = {pa.x, pa.y, pa.z, pa.w};
            float vv[4] = {vb.x, vb.y, vb.z, vb.w};
#pragma unroll
            for (int ii = 0; ii < 4; ii++)
#pragma unroll
                for (int jj = 0; jj < 4; jj++)
                    o[ii * 4 + jj] += pp[ii] * vv[jj];
        }
    }

#pragma unroll
    for (int ii = 0; ii < 4; ii++) {
        int gi = q0 + ty * 4 + ii;
        float inv = 1.0f / l_run[ii];
        float4 ov = make_float4(o[ii*4+0]*inv, o[ii*4+1]*inv, o[ii*4+2]*inv, o[ii*4+3]*inv);
        *(float4*)(&attn_out[((size_t)(b * SEQ + gi)) * DIM + h * HD + tx * 4]) = ov;
    }
}

// ---------------------------------------------------------------------------
extern "C" void kernel_launch(void* const* d_in, const int* in_sizes, int n_in,
                              void* d_out, int out_size)
{
    const float* x    = (const float*)d_in[0];   // (2,2048,1024)
    const float* Wqkv = (const float*)d_in[1];   // (3072,1024)
    const float* Wo   = (const float*)d_in[2];   // (1024,1024)
    float* out = (float*)d_out;

    float *qkv, *attn;
    __nv_bfloat16 *xhi, *xlo, *wqh, *wql, *woh, *wol, *ahi, *alo;
    cudaGetSymbolAddress((void**)&qkv,  g_qkv);
    cudaGetSymbolAddress((void**)&attn, g_attn);
    cudaGetSymbolAddress((void**)&xhi,  g_xhi);
    cudaGetSymbolAddress((void**)&xlo,  g_xlo);
    cudaGetSymbolAddress((void**)&wqh,  g_wqh);
    cudaGetSymbolAddress((void**)&wql,  g_wql);
    cudaGetSymbolAddress((void**)&woh,  g_woh);
    cudaGetSymbolAddress((void**)&wol,  g_wol);
    cudaGetSymbolAddress((void**)&ahi,  g_ahi);
    cudaGetSymbolAddress((void**)&alo,  g_alo);

    cudaFuncSetAttribute(gemm_bf16x3, cudaFuncAttributeMaxDynamicSharedMemorySize, GEMM_SMEM);

    // hi/lo splits of x and weights
    {
        int n4 = NTOK * DIM / 4;
        split_bf16<<<(n4 + 255) / 256, 256>>>(x, xhi, xlo, n4);
        n4 = 3 * DIM * DIM / 4;
        split_bf16<<<(n4 + 255) / 256, 256>>>(Wqkv, wqh, wql, n4);
        n4 = DIM * DIM / 4;
        split_bf16<<<(n4 + 255) / 256, 256>>>(Wo, woh, wol, n4);
    }

    // 1) qkv = x @ Wqkv^T   (M=4096, N=3072, K=1024)
    {
        dim3 grid(3 * DIM / BN, NTOK / BM);   // (12, 32)
        gemm_bf16x3<<<grid, 256, GEMM_SMEM>>>(xhi, xlo, wqh, wql, qkv, DIM, 3 * DIM);
    }

    // 2) flash attention (fp32)
    {
        int smem = 3 * HD * LDA * sizeof(float);
        cudaFuncSetAttribute(attn_kernel, cudaFuncAttributeMaxDynamicSharedMemorySize, smem);
        dim3 grid(SEQ / 64, BATCH * HEADS);
        attn_kernel<<<grid, 256, smem>>>(qkv, attn);
    }

    // 3) split attn, then out = attn @ Wo^T  (M=4096, N=1024, K=1024)
    {
        int n4 = NTOK * DIM / 4;
        split_bf16<<<(n4 + 255) / 256, 256>>>(attn, ahi, alo, n4);
        dim3 grid(DIM / BN, NTOK / BM);       // (4, 32)
        gemm_bf16x3<<<grid, 256, GEMM_SMEM>>>(ahi, alo, woh, wol, out, DIM, DIM);
    }
}

// round 4
// speedup vs baseline: 2.3171x; 1.5907x over previous
#include <cuda_runtime.h>
#include <cuda_bf16.h>
#include <cstdint>

// Problem constants
#define BATCH 2
#define SEQ   2048
#define DIM   1024
#define HEADS 16
#define HD    64
#define NTOK  (BATCH*SEQ)   // 4096

// ---------------------------------------------------------------------------
// Scratch (__device__ globals; allocation-free rule)
// ---------------------------------------------------------------------------
__device__ float g_qkv [(size_t)NTOK * 3 * DIM];    // 4096 x 3072 fp32
__device__ __nv_bfloat16 g_xhi[(size_t)NTOK * DIM];
__device__ __nv_bfloat16 g_xlo[(size_t)NTOK * DIM];
__device__ __nv_bfloat16 g_wqh[(size_t)3 * DIM * DIM];
__device__ __nv_bfloat16 g_wql[(size_t)3 * DIM * DIM];
__device__ __nv_bfloat16 g_woh[(size_t)DIM * DIM];
__device__ __nv_bfloat16 g_wol[(size_t)DIM * DIM];
__device__ __nv_bfloat16 g_ahi[(size_t)NTOK * DIM];
__device__ __nv_bfloat16 g_alo[(size_t)NTOK * DIM];

// ---------------------------------------------------------------------------
// PTX helpers (baseline sm_100-safe)
// ---------------------------------------------------------------------------
__device__ __forceinline__ uint32_t smem_u32(const void* p) {
    uint32_t a;
    asm("{ .reg .u64 t; cvta.to.shared.u64 t, %1; cvt.u32.u64 %0, t; }" : "=r"(a) : "l"(p));
    return a;
}
#define SWZ64(off)  ((off) ^ (((off) >> 3) & 0x30))
#define SWZ128(off) ((off) ^ (((off) >> 3) & 0x70))

#define CP_ASYNC16(saddr, gptr) \
    asm volatile("cp.async.cg.shared.global [%0], [%1], 16;\n" :: "r"(saddr), "l"(gptr))
#define CP_COMMIT() asm volatile("cp.async.commit_group;\n" ::: "memory")
#define CP_WAIT(N)  asm volatile("cp.async.wait_group %0;\n" :: "n"(N) : "memory")

#define LDSM_X4(r0, r1, r2, r3, addr) \
    asm volatile("ldmatrix.sync.aligned.m8n8.x4.shared.b16 {%0,%1,%2,%3}, [%4];" \
                 : "=r"(r0), "=r"(r1), "=r"(r2), "=r"(r3) : "r"(addr))
#define LDSM_X4_T(r0, r1, r2, r3, addr) \
    asm volatile("ldmatrix.sync.aligned.m8n8.x4.trans.shared.b16 {%0,%1,%2,%3}, [%4];" \
                 : "=r"(r0), "=r"(r1), "=r"(r2), "=r"(r3) : "r"(addr))

#define MMA16816(c, a, b0, b1) \
    asm volatile("mma.sync.aligned.m16n8k16.row.col.f32.bf16.bf16.f32 " \
                 "{%0,%1,%2,%3}, {%4,%5,%6,%7}, {%8,%9}, {%0,%1,%2,%3};" \
                 : "+f"((c)[0]), "+f"((c)[1]), "+f"((c)[2]), "+f"((c)[3]) \
                 : "r"((a)[0]), "r"((a)[1]), "r"((a)[2]), "r"((a)[3]), \
                   "r"(b0), "r"(b1))

__device__ __forceinline__ uint32_t pack_bf2(float a, float b) {
    __nv_bfloat162 v(__float2bfloat16(a), __float2bfloat16(b));
    return *(uint32_t*)&v;
}

// ---------------------------------------------------------------------------
// split kernel: hi = bf16(x), lo = bf16(x - hi)
// ---------------------------------------------------------------------------
__global__ void split_bf16(const float* __restrict__ src, __nv_bfloat16* __restrict__ hi,
                           __nv_bfloat16* __restrict__ lo, int n4)
{
    int i = blockIdx.x * blockDim.x + threadIdx.x;
    if (i >= n4) return;
    float4 v = ((const float4*)src)[i];
    __nv_bfloat16 h0 = __float2bfloat16(v.x);
    __nv_bfloat16 h1 = __float2bfloat16(v.y);
    __nv_bfloat16 h2 = __float2bfloat16(v.z);
    __nv_bfloat16 h3 = __float2bfloat16(v.w);
    __nv_bfloat16 l0 = __float2bfloat16(v.x - __bfloat162float(h0));
    __nv_bfloat16 l1 = __float2bfloat16(v.y - __bfloat162float(h1));
    __nv_bfloat16 l2 = __float2bfloat16(v.z - __bfloat162float(h2));
    __nv_bfloat16 l3 = __float2bfloat16(v.w - __bfloat162float(h3));
    __nv_bfloat162* hp = (__nv_bfloat162*)(hi + (size_t)i * 4);
    __nv_bfloat162* lp = (__nv_bfloat162*)(lo + (size_t)i * 4);
    hp[0] = __nv_bfloat162(h0, h1);
    hp[1] = __nv_bfloat162(h2, h3);
    lp[0] = __nv_bfloat162(l0, l1);
    lp[1] = __nv_bfloat162(l2, l3);
}

// ---------------------------------------------------------------------------
// 3-term bf16 GEMM via mma.sync:  C[M][N] = A[M][K] * B[N][K]^T  (fp32 out)
// (unchanged from round 3 — passed at 276 TF/s effective)
// ---------------------------------------------------------------------------
#define BM 128
#define BN 256
#define BK 32
#define NSTAGE 4
#define A_BYTES (BM * BK * 2)
#define B_BYTES (BN * BK * 2)
#define STAGE_B (2*A_BYTES + 2*B_BYTES)
#define GEMM_SMEM (NSTAGE * STAGE_B)

__global__ __launch_bounds__(256)
void gemm_bf16x3(const __nv_bfloat16* __restrict__ Ahi, const __nv_bfloat16* __restrict__ Alo,
                 const __nv_bfloat16* __restrict__ Bhi, const __nv_bfloat16* __restrict__ Blo,
                 float* __restrict__ C, int K, int Ntot)
{
    extern __shared__ __align__(1024) char smem[];
    const uint32_t sbase = smem_u32(smem);
    const int tid  = threadIdx.x;
    const int wid  = tid >> 5;
    const int lane = tid & 31;
    const int m0 = blockIdx.y * BM;
    const int n0 = blockIdx.x * BN;

    const int wm = wid & 1;
    const int wn = wid >> 1;
    const int m_off = wm * 64;
    const int n_off = wn * 64;

    const __nv_bfloat16* aS[2] = { Ahi + (size_t)m0 * K, Alo + (size_t)m0 * K };
    const __nv_bfloat16* bS[2] = { Bhi + (size_t)n0 * K, Blo + (size_t)n0 * K };

    const int NIT = K / BK;

    auto load_stage = [&](int sbuf, int k0) {
        uint32_t stg = sbase + sbuf * STAGE_B;
#pragma unroll
        for (int p = 0; p < 2; p++) {
            uint32_t part = stg + p * A_BYTES;
            const __nv_bfloat16* src = aS[p] + k0;
#pragma unroll
            for (int r = 0; r < 2; r++) {
                int idx = r * 256 + tid;
                int row = idx >> 2, c = idx & 3;
                uint32_t soff = SWZ64((uint32_t)(row * 64 + c * 16));
                CP_ASYNC16(part + soff, src + (size_t)row * K + c * 8);
            }
        }
#pragma unroll
        for (int p = 0; p < 2; p++) {
            uint32_t part = stg + 2 * A_BYTES + p * B_BYTES;
            const __nv_bfloat16* src = bS[p] + k0;
#pragma unroll
            for (int r = 0; r < 4; r++) {
                int idx = r * 256 + tid;
                int row = idx >> 2, c = idx & 3;
                uint32_t soff = SWZ64((uint32_t)(row * 64 + c * 16));
                CP_ASYNC16(part + soff, src + (size_t)row * K + c * 8);
            }
        }
    };

    float c[4][8][4];
#pragma unroll
    for (int i = 0; i < 4; i++)
#pragma unroll
        for (int j = 0; j < 8; j++)
#pragma unroll
            for (int t = 0; t < 4; t++) c[i][j][t] = 0.f;

#pragma unroll
    for (int s = 0; s < 3; s++) { load_stage(s, s * BK); CP_COMMIT(); }

    const int lr = lane & 15;
    const int lk = lane >> 4;

    for (int it = 0; it < NIT; it++) {
        CP_WAIT(2);
        __syncthreads();
        if (it + 3 < NIT) { load_stage((it + 3) & 3, (it + 3) * BK); CP_COMMIT(); }

        uint32_t stg  = sbase + (it & 3) * STAGE_B;
        uint32_t aHiB = stg;
        uint32_t aLoB = stg + A_BYTES;
        uint32_t bHiB = stg + 2 * A_BYTES;
        uint32_t bLoB = stg + 2 * A_BYTES + B_BYTES;

#pragma unroll
        for (int ks = 0; ks < 2; ks++) {
            uint32_t ahi[4][4], alo[4][4];
#pragma unroll
            for (int mi = 0; mi < 4; mi++) {
                uint32_t off = (uint32_t)((m_off + mi * 16 + lr) * 64 + ks * 32 + lk * 16);
                uint32_t sw = SWZ64(off);
                LDSM_X4(ahi[mi][0], ahi[mi][1], ahi[mi][2], ahi[mi][3], aHiB + sw);
                LDSM_X4(alo[mi][0], alo[mi][1], alo[mi][2], alo[mi][3], aLoB + sw);
            }
#pragma unroll
            for (int ng = 0; ng < 4; ng++) {
                uint32_t off = (uint32_t)((n_off + ng * 16 + lr) * 64 + ks * 32 + lk * 16);
                uint32_t sw = SWZ64(off);
                uint32_t bh0, bh1, bh2, bh3, bl0, bl1, bl2, bl3;
                LDSM_X4(bh0, bh1, bh2, bh3, bHiB + sw);
                LDSM_X4(bl0, bl1, bl2, bl3, bLoB + sw);
#pragma unroll
                for (int mi = 0; mi < 4; mi++) {
                    MMA16816(c[mi][ng*2+0], ahi[mi], bh0, bh2);
                    MMA16816(c[mi][ng*2+1], ahi[mi], bh1, bh3);
                    MMA16816(c[mi][ng*2+0], alo[mi], bh0, bh2);
                    MMA16816(c[mi][ng*2+1], alo[mi], bh1, bh3);
                    MMA16816(c[mi][ng*2+0], ahi[mi], bl0, bl2);
                    MMA16816(c[mi][ng*2+1], ahi[mi], bl1, bl3);
                }
            }
        }
    }

    const int cr = lane >> 2;
    const int cc = (lane & 3) * 2;
#pragma unroll
    for (int mi = 0; mi < 4; mi++) {
        int r0 = m0 + m_off + mi * 16 + cr;
#pragma unroll
        for (int j = 0; j < 8; j++) {
            int col = n0 + n_off + j * 8 + cc;
            float2 v0 = make_float2(c[mi][j][0], c[mi][j][1]);
            float2 v1 = make_float2(c[mi][j][2], c[mi][j][3]);
            *(float2*)(C + (size_t)r0 * Ntot + col)       = v0;
            *(float2*)(C + (size_t)(r0 + 8) * Ntot + col) = v1;
        }
    }
}

// ---------------------------------------------------------------------------
// Tensor-core flash attention with ALiBi + causal mask.
// CTA: 128 queries x one (b,h); 8 warps x 16 query rows.
// K/V tiles of 64 keys, hi/lo bf16 split, double-buffered (register prefetch).
// S = QK^T 3-term; softmax fp32 in fragments; PV 3-term (P,V hi/lo).
// Writes attention output directly as bf16 hi/lo for the final GEMM.
// ---------------------------------------------------------------------------
// smem layout (bytes):
//   QHI 0       (128 rows x 128B = 16384)
//   QLO 16384
//   stage s (s=0,1) at 32768 + s*32768:
//      KHI +0, KLO +8192, VHI +16384, VLO +24576   (each 64 x 128B = 8192)
//   PHI 98304 (128 x 128B = 16384)
//   PLO 114688
#define ATT_SMEM 131072
#define Q_HI 0
#define Q_LO 16384
#define STG0 32768
#define P_HI 98304
#define P_LO 114688

__global__ __launch_bounds__(256, 1)
void attn_mma(const float* __restrict__ qkv,
              __nv_bfloat16* __restrict__ out_hi, __nv_bfloat16* __restrict__ out_lo)
{
    extern __shared__ __align__(1024) char smem[];
    const uint32_t sbase = smem_u32(smem);
    const int tid  = threadIdx.x;
    const int wid  = tid >> 5;
    const int lane = tid & 31;
    const int lr   = lane & 15;
    const int lk   = lane >> 4;

    const int qt = blockIdx.x;            // 0..15
    const int bh = blockIdx.y;            // 0..31
    const int b  = bh >> 4;
    const int h  = bh & 15;
    const int q0 = qt * 128;

    const float slope = exp2f(-0.5f * (float)(h + 1));
    const float scale = 0.125f;

    const size_t rs = 3 * DIM;
    const float* qbase = qkv + (size_t)b * SEQ * rs + h * HD;
    const float* kbase = qbase + DIM;
    const float* vbase = qbase + 2 * DIM;

    // ---- load Q tile (128x64 fp32), scale, split hi/lo, store swizzled ----
#pragma unroll
    for (int r = 0; r < 8; r++) {
        int idx = r * 256 + tid;          // 0..2047 float4 chunks
        int row = idx >> 4;               // 0..127
        int c4  = idx & 15;               // float4 index within row
        float4 v = *(const float4*)(qbase + (size_t)(q0 + row) * rs + c4 * 4);
        v.x *= scale; v.y *= scale; v.z *= scale; v.w *= scale;
        __nv_bfloat16 hx = __float2bfloat16(v.x), hy = __float2bfloat16(v.y);
        __nv_bfloat16 hz = __float2bfloat16(v.z), hw = __float2bfloat16(v.w);
        uint32_t soff = SWZ128((uint32_t)(row * 128 + c4 * 8));
        uint2 hv, lv;
        hv.x = pack_bf2(v.x, v.y); hv.y = pack_bf2(v.z, v.w);
        lv.x = pack_bf2(v.x - __bfloat162float(hx), v.y - __bfloat162float(hy));
        lv.y = pack_bf2(v.z - __bfloat162float(hz), v.w - __bfloat162float(hw));
        *(uint2*)(smem + Q_HI + soff) = hv;
        *(uint2*)(smem + Q_LO + soff) = lv;
    }

    // ---- per-thread K/V prefetch registers (one 64x64 tile each) ----
    // thread -> row = tid>>2 (0..63), c4 = (tid&3)*4 + i
    float4 kreg[4], vreg[4];
    const int pr_row = tid >> 2;
    const int pr_c4  = (tid & 3) * 4;

    auto load_kv = [&](int kt) {
        const float* kp = kbase + (size_t)(kt * 64 + pr_row) * rs + pr_c4 * 4;
        const float* vp = vbase + (size_t)(kt * 64 + pr_row) * rs + pr_c4 * 4;
#pragma unroll
        for (int i = 0; i < 4; i++) {
            kreg[i] = *(const float4*)(kp + i * 4);
            vreg[i] = *(const float4*)(vp + i * 4);
        }
    };
    auto store_kv = [&](int s) {
        uint32_t stg = sbase + STG0 + s * 32768;
#pragma unroll
        for (int i = 0; i < 4; i++) {
            uint32_t soff = SWZ128((uint32_t)(pr_row * 128 + (pr_c4 + i) * 8));
            float4 kv = kreg[i], vv = vreg[i];
            __nv_bfloat16 khx = __float2bfloat16(kv.x), khy = __float2bfloat16(kv.y);
            __nv_bfloat16 khz = __float2bfloat16(kv.z), khw = __float2bfloat16(kv.w);
            uint2 t;
            t.x = pack_bf2(kv.x, kv.y); t.y = pack_bf2(kv.z, kv.w);
            *(uint2*)(smem + 0) = t;   // placeholder avoided below
            // K hi
            *(uint2*)((char*)nullptr) = t; // never reached
        }
    };
    (void)store_kv; // replaced by explicit code below

    float cs[8][4];
    float co[8][4];
#pragma unroll
    for (int j = 0; j < 8; j++)
#pragma unroll
        for (int t = 0; t < 4; t++) co[j][t] = 0.f;

    float m0v = -1e30f, m1v = -1e30f, l0v = 0.f, l1v = 0.f;

    const int r0 = lane >> 2;             // accumulator row (0..7), +8 for second
    const int ccol = (lane & 3) * 2;
    const int gi0 = q0 + wid * 16 + r0;
    const int gi1 = gi0 + 8;

    const int nkt = 2 * qt + 2;
    load_kv(0);

    for (int kt = 0; kt < nkt; kt++) {
        const int s = kt & 1;
        const int k0 = kt * 64;
        uint32_t stg = sbase + STG0 + s * 32768;

        // store prefetched K/V (fp32 regs -> bf16 hi/lo smem, swizzled)
#pragma unroll
        for (int i = 0; i < 4; i++) {
            uint32_t soff = SWZ128((uint32_t)(pr_row * 128 + (pr_c4 + i) * 8));
            float4 kv = kreg[i];
            __nv_bfloat16 ax = __float2bfloat16(kv.x), ay = __float2bfloat16(kv.y);
            __nv_bfloat16 az = __float2bfloat16(kv.z), aw = __float2bfloat16(kv.w);
            uint2 hv, lv;
            hv.x = pack_bf2(kv.x, kv.y); hv.y = pack_bf2(kv.z, kv.w);
            lv.x = pack_bf2(kv.x - __bfloat162float(ax), kv.y - __bfloat162float(ay));
            lv.y = pack_bf2(kv.z - __bfloat162float(az), kv.w - __bfloat162float(aw));
            *(uint2*)(smem + (stg - sbase) + 0    + soff) = hv;
            *(uint2*)(smem + (stg - sbase) + 8192 + soff) = lv;
            float4 vv = vreg[i];
            __nv_bfloat16 bx = __float2bfloat16(vv.x), by = __float2bfloat16(vv.y);
            __nv_bfloat16 bz = __float2bfloat16(vv.z), bw = __float2bfloat16(vv.w);
            uint2 hv2, lv2;
            hv2.x = pack_bf2(vv.x, vv.y); hv2.y = pack_bf2(vv.z, vv.w);
            lv2.x = pack_bf2(vv.x - __bfloat162float(bx), vv.y - __bfloat162float(by));
            lv2.y = pack_bf2(vv.z - __bfloat162float(bz), vv.w - __bfloat162float(bw));
            *(uint2*)(smem + (stg - sbase) + 16384 + soff) = hv2;
            *(uint2*)(smem + (stg - sbase) + 24576 + soff) = lv2;
        }
        __syncthreads();

        if (kt + 1 < nkt) load_kv(kt + 1);

        // ---- S = Q K^T (3-term) ----
#pragma unroll
        for (int j = 0; j < 8; j++)
#pragma unroll
            for (int t = 0; t < 4; t++) cs[j][t] = 0.f;

        uint32_t kHiB = stg, kLoB = stg + 8192;
#pragma unroll
        for (int ks = 0; ks < 4; ks++) {
            uint32_t qoff = SWZ128((uint32_t)((wid * 16 + lr) * 128 + ks * 32 + lk * 16));
            uint32_t ahi[4], alo[4];
            LDSM_X4(ahi[0], ahi[1], ahi[2], ahi[3], sbase + Q_HI + qoff);
            LDSM_X4(alo[0], alo[1], alo[2], alo[3], sbase + Q_LO + qoff);
#pragma unroll
            for (int ng = 0; ng < 4; ng++) {
                uint32_t boff = SWZ128((uint32_t)((ng * 16 + lr) * 128 + ks * 32 + lk * 16));
                uint32_t bh0, bh1, bh2, bh3, bl0, bl1, bl2, bl3;
                LDSM_X4(bh0, bh1, bh2, bh3, kHiB + boff);
                LDSM_X4(bl0, bl1, bl2, bl3, kLoB + boff);
                MMA16816(cs[ng*2+0], ahi, bh0, bh2);
                MMA16816(cs[ng*2+1], ahi, bh1, bh3);
                MMA16816(cs[ng*2+0], alo, bh0, bh2);
                MMA16816(cs[ng*2+1], alo, bh1, bh3);
                MMA16816(cs[ng*2+0], ahi, bl0, bl2);
                MMA16816(cs[ng*2+1], ahi, bl1, bl3);
            }
        }

        // ---- ALiBi + causal mask ----
#pragma unroll
        for (int nb = 0; nb < 8; nb++) {
#pragma unroll
            for (int c = 0; c < 2; c++) {
                int gj = k0 + nb * 8 + ccol + c;
                float rel0 = slope * (float)(gj - gi0);
                float rel1 = slope * (float)(gj - gi1);
                cs[nb][c]     = (gj > gi0) ? -1e30f : cs[nb][c]     - rel0;
                cs[nb][2 + c] = (gj > gi1) ? -1e30f : cs[nb][2 + c] - rel1;
            }
        }

        // ---- online softmax ----
        float mx0 = -1e30f, mx1 = -1e30f;
#pragma unroll
        for (int nb = 0; nb < 8; nb++) {
            mx0 = fmaxf(mx0, fmaxf(cs[nb][0], cs[nb][1]));
            mx1 = fmaxf(mx1, fmaxf(cs[nb][2], cs[nb][3]));
        }
        mx0 = fmaxf(mx0, __shfl_xor_sync(0xffffffff, mx0, 1));
        mx0 = fmaxf(mx0, __shfl_xor_sync(0xffffffff, mx0, 2));
        mx1 = fmaxf(mx1, __shfl_xor_sync(0xffffffff, mx1, 1));
        mx1 = fmaxf(mx1, __shfl_xor_sync(0xffffffff, mx1, 2));

        float mn0 = fmaxf(m0v, mx0), mn1 = fmaxf(m1v, mx1);
        float corr0 = __expf(m0v - mn0), corr1 = __expf(m1v - mn1);
        m0v = mn0; m1v = mn1;

        float sum0 = 0.f, sum1 = 0.f;
        const int prow0 = wid * 16 + r0;
#pragma unroll
        for (int nb = 0; nb < 8; nb++) {
            float p00 = __expf(cs[nb][0] - mn0);
            float p01 = __expf(cs[nb][1] - mn0);
            float p10 = __expf(cs[nb][2] - mn1);
            float p11 = __expf(cs[nb][3] - mn1);
            sum0 += p00 + p01;
            sum1 += p10 + p11;
            // pack + store P hi/lo (per-warp rows; no cross-warp readers)
            uint32_t off0 = SWZ128((uint32_t)(prow0 * 128 + nb * 16 + (lane & 3) * 4));
            uint32_t off1 = SWZ128((uint32_t)((prow0 + 8) * 128 + nb * 16 + (lane & 3) * 4));
            __nv_bfloat16 h00 = __float2bfloat16(p00), h01 = __float2bfloat16(p01);
            __nv_bfloat16 h10 = __float2bfloat16(p10), h11 = __float2bfloat16(p11);
            *(uint32_t*)(smem + P_HI + off0) = pack_bf2(p00, p01);
            *(uint32_t*)(smem + P_HI + off1) = pack_bf2(p10, p11);
            *(uint32_t*)(smem + P_LO + off0) =
                pack_bf2(p00 - __bfloat162float(h00), p01 - __bfloat162float(h01));
            *(uint32_t*)(smem + P_LO + off1) =
                pack_bf2(p10 - __bfloat162float(h10), p11 - __bfloat162float(h11));
        }
        sum0 += __shfl_xor_sync(0xffffffff, sum0, 1);
        sum0 += __shfl_xor_sync(0xffffffff, sum0, 2);
        sum1 += __shfl_xor_sync(0xffffffff, sum1, 1);
        sum1 += __shfl_xor_sync(0xffffffff, sum1, 2);
        l0v = l0v * corr0 + sum0;
        l1v = l1v * corr1 + sum1;

#pragma unroll
        for (int nb = 0; nb < 8; nb++) {
            co[nb][0] *= corr0; co[nb][1] *= corr0;
            co[nb][2] *= corr1; co[nb][3] *= corr1;
        }
        __syncwarp();

        // ---- O += P V (3-term; V via ldmatrix.trans) ----
        uint32_t vHiB = stg + 16384, vLoB = stg + 24576;
#pragma unroll
        for (int ks = 0; ks < 4; ks++) {        // key steps of 16
            uint32_t poff = SWZ128((uint32_t)((wid * 16 + lr) * 128 + ks * 32 + lk * 16));
            uint32_t phi[4], plo[4];
            LDSM_X4(phi[0], phi[1], phi[2], phi[3], sbase + P_HI + poff);
            LDSM_X4(plo[0], plo[1], plo[2], plo[3], sbase + P_LO + poff);
#pragma unroll
            for (int ng = 0; ng < 4; ng++) {    // d groups of 16
                uint32_t voff = SWZ128((uint32_t)((ks * 16 + lr) * 128 + ng * 32 + lk * 16));
                uint32_t vh0, vh1, vh2, vh3, vl0, vl1, vl2, vl3;
                LDSM_X4_T(vh0, vh1, vh2, vh3, vHiB + voff);
                LDSM_X4_T(vl0, vl1, vl2, vl3, vLoB + voff);
                MMA16816(co[ng*2+0], phi, vh0, vh1);
                MMA16816(co[ng*2+1], phi, vh2, vh3);
                MMA16816(co[ng*2+0], plo, vh0, vh1);
                MMA16816(co[ng*2+1], plo, vh2, vh3);
                MMA16816(co[ng*2+0], phi, vl0, vl1);
                MMA16816(co[ng*2+1], phi, vl2, vl3);
            }
        }
        __syncthreads();
    }

    // ---- normalize + write bf16 hi/lo directly ----
    float inv0 = 1.0f / l0v, inv1 = 1.0f / l1v;
    size_t row0 = (size_t)(b * SEQ + gi0) * DIM + h * HD;
    size_t row1 = (size_t)(b * SEQ + gi1) * DIM + h * HD;
#pragma unroll
    for (int nb = 0; nb < 8; nb++) {
        int d = nb * 8 + ccol;
        float o00 = co[nb][0] * inv0, o01 = co[nb][1] * inv0;
        float o10 = co[nb][2] * inv1, o11 = co[nb][3] * inv1;
        __nv_bfloat16 h00 = __float2bfloat16(o00), h01 = __float2bfloat16(o01);
        __nv_bfloat16 h10 = __float2bfloat16(o10), h11 = __float2bfloat16(o11);
        *(uint32_t*)(out_hi + row0 + d) = pack_bf2(o00, o01);
        *(uint32_t*)(out_hi + row1 + d) = pack_bf2(o10, o11);
        *(uint32_t*)(out_lo + row0 + d) =
            pack_bf2(o00 - __bfloat162float(h00), o01 - __bfloat162float(h01));
        *(uint32_t*)(out_lo + row1 + d) =
            pack_bf2(o10 - __bfloat162float(h10), o11 - __bfloat162float(h11));
    }
}

// ---------------------------------------------------------------------------
extern "C" void kernel_launch(void* const* d_in, const int* in_sizes, int n_in,
                              void* d_out, int out_size)
{
    const float* x    = (const float*)d_in[0];
    const float* Wqkv = (const float*)d_in[1];
    const float* Wo   = (const float*)d_in[2];
    float* out = (float*)d_out;

    float *qkv;
    __nv_bfloat16 *xhi, *xlo, *wqh, *wql, *woh, *wol, *ahi, *alo;
    cudaGetSymbolAddress((void**)&qkv,  g_qkv);
    cudaGetSymbolAddress((void**)&xhi,  g_xhi);
    cudaGetSymbolAddress((void**)&xlo,  g_xlo);
    cudaGetSymbolAddress((void**)&wqh,  g_wqh);
    cudaGetSymbolAddress((void**)&wql,  g_wql);
    cudaGetSymbolAddress((void**)&woh,  g_woh);
    cudaGetSymbolAddress((void**)&wol,  g_wol);
    cudaGetSymbolAddress((void**)&ahi,  g_ahi);
    cudaGetSymbolAddress((void**)&alo,  g_alo);

    cudaFuncSetAttribute(gemm_bf16x3, cudaFuncAttributeMaxDynamicSharedMemorySize, GEMM_SMEM);
    cudaFuncSetAttribute(attn_mma,    cudaFuncAttributeMaxDynamicSharedMemorySize, ATT_SMEM);

    // hi/lo splits of x and weights
    {
        int n4 = NTOK * DIM / 4;
        split_bf16<<<(n4 + 255) / 256, 256>>>(x, xhi, xlo, n4);
        n4 = 3 * DIM * DIM / 4;
        split_bf16<<<(n4 + 255) / 256, 256>>>(Wqkv, wqh, wql, n4);
        n4 = DIM * DIM / 4;
        split_bf16<<<(n4 + 255) / 256, 256>>>(Wo, woh, wol, n4);
    }

    // 1) qkv = x @ Wqkv^T
    {
        dim3 grid(3 * DIM / BN, NTOK / BM);
        gemm_bf16x3<<<grid, 256, GEMM_SMEM>>>(xhi, xlo, wqh, wql, qkv, DIM, 3 * DIM);
    }

    // 2) tensor-core flash attention (writes bf16 hi/lo directly)
    {
        dim3 grid(SEQ / 128, BATCH * HEADS);   // (16, 32)
        attn_mma<<<grid, 256, ATT_SMEM>>>(qkv, ahi, alo);
    }

    // 3) out = attn @ Wo^T
    {
        dim3 grid(DIM / BN, NTOK / BM);
        gemm_bf16x3<<<grid, 256, GEMM_SMEM>>>(ahi, alo, woh, wol, out, DIM, DIM);
    }
}

// round 5
// speedup vs baseline: 2.3972x; 1.0346x over previous
#include <cuda_runtime.h>
#include <cuda_bf16.h>
#include <cstdint>

// Problem constants
#define BATCH 2
#define SEQ   2048
#define DIM   1024
#define HEADS 16
#define HD    64
#define NTOK  (BATCH*SEQ)   // 4096

// ---------------------------------------------------------------------------
// Scratch (__device__ globals; allocation-free rule)
// ---------------------------------------------------------------------------
__device__ float g_qkv [(size_t)NTOK * 3 * DIM];    // 4096 x 3072 fp32
__device__ __nv_bfloat16 g_xhi[(size_t)NTOK * DIM];
__device__ __nv_bfloat16 g_xlo[(size_t)NTOK * DIM];
__device__ __nv_bfloat16 g_wqh[(size_t)3 * DIM * DIM];
__device__ __nv_bfloat16 g_wql[(size_t)3 * DIM * DIM];
__device__ __nv_bfloat16 g_woh[(size_t)DIM * DIM];
__device__ __nv_bfloat16 g_wol[(size_t)DIM * DIM];
__device__ __nv_bfloat16 g_ahi[(size_t)NTOK * DIM];
__device__ __nv_bfloat16 g_alo[(size_t)NTOK * DIM];

// ---------------------------------------------------------------------------
// PTX helpers (baseline sm_100-safe)
// ---------------------------------------------------------------------------
__device__ __forceinline__ uint32_t smem_u32(const void* p) {
    uint32_t a;
    asm("{ .reg .u64 t; cvta.to.shared.u64 t, %1; cvt.u32.u64 %0, t; }" : "=r"(a) : "l"(p));
    return a;
}
#define SWZ64(off)  ((off) ^ (((off) >> 3) & 0x30))
#define SWZ128(off) ((off) ^ (((off) >> 3) & 0x70))

#define CP_ASYNC16(saddr, gptr) \
    asm volatile("cp.async.cg.shared.global [%0], [%1], 16;\n" :: "r"(saddr), "l"(gptr))
#define CP_COMMIT() asm volatile("cp.async.commit_group;\n" ::: "memory")
#define CP_WAIT(N)  asm volatile("cp.async.wait_group %0;\n" :: "n"(N) : "memory")

#define LDSM_X4(r0, r1, r2, r3, addr) \
    asm volatile("ldmatrix.sync.aligned.m8n8.x4.shared.b16 {%0,%1,%2,%3}, [%4];" \
                 : "=r"(r0), "=r"(r1), "=r"(r2), "=r"(r3) : "r"(addr))
#define LDSM_X4_T(r0, r1, r2, r3, addr) \
    asm volatile("ldmatrix.sync.aligned.m8n8.x4.trans.shared.b16 {%0,%1,%2,%3}, [%4];" \
                 : "=r"(r0), "=r"(r1), "=r"(r2), "=r"(r3) : "r"(addr))

#define MMA16816(c, a, b0, b1) \
    asm volatile("mma.sync.aligned.m16n8k16.row.col.f32.bf16.bf16.f32 " \
                 "{%0,%1,%2,%3}, {%4,%5,%6,%7}, {%8,%9}, {%0,%1,%2,%3};" \
                 : "+f"((c)[0]), "+f"((c)[1]), "+f"((c)[2]), "+f"((c)[3]) \
                 : "r"((a)[0]), "r"((a)[1]), "r"((a)[2]), "r"((a)[3]), \
                   "r"(b0), "r"(b1))

__device__ __forceinline__ uint32_t pack_bf2(float a, float b) {
    __nv_bfloat162 v(__float2bfloat16(a), __float2bfloat16(b));
    return *(uint32_t*)&v;
}

// ---------------------------------------------------------------------------
// split kernel: hi = bf16(x), lo = bf16(x - hi)
// ---------------------------------------------------------------------------
__global__ void split_bf16(const float* __restrict__ src, __nv_bfloat16* __restrict__ hi,
                           __nv_bfloat16* __restrict__ lo, int n4)
{
    int i = blockIdx.x * blockDim.x + threadIdx.x;
    if (i >= n4) return;
    float4 v = ((const float4*)src)[i];
    __nv_bfloat16 h0 = __float2bfloat16(v.x);
    __nv_bfloat16 h1 = __float2bfloat16(v.y);
    __nv_bfloat16 h2 = __float2bfloat16(v.z);
    __nv_bfloat16 h3 = __float2bfloat16(v.w);
    __nv_bfloat16 l0 = __float2bfloat16(v.x - __bfloat162float(h0));
    __nv_bfloat16 l1 = __float2bfloat16(v.y - __bfloat162float(h1));
    __nv_bfloat16 l2 = __float2bfloat16(v.z - __bfloat162float(h2));
    __nv_bfloat16 l3 = __float2bfloat16(v.w - __bfloat162float(h3));
    __nv_bfloat162* hp = (__nv_bfloat162*)(hi + (size_t)i * 4);
    __nv_bfloat162* lp = (__nv_bfloat162*)(lo + (size_t)i * 4);
    hp[0] = __nv_bfloat162(h0, h1);
    hp[1] = __nv_bfloat162(h2, h3);
    lp[0] = __nv_bfloat162(l0, l1);
    lp[1] = __nv_bfloat162(l2, l3);
}

// ---------------------------------------------------------------------------
// 3-term bf16 GEMM via mma.sync:  C[M][N] = A[M][K] * B[N][K]^T  (fp32 out)
// CTA tile 128x128, BK=32, 3 stages, 8 warps (64x32 tiles), 2 CTAs/SM.
// ---------------------------------------------------------------------------
#define BM 128
#define BN 128
#define BK 32
#define NSTAGE 3
#define A_BYTES (BM * BK * 2)            // 8192 per term
#define B_BYTES (BN * BK * 2)            // 8192 per term
#define STAGE_B (2*A_BYTES + 2*B_BYTES)  // 32768
#define GEMM_SMEM (NSTAGE * STAGE_B)     // 98304

__global__ __launch_bounds__(256, 2)
void gemm_bf16x3(const __nv_bfloat16* __restrict__ Ahi, const __nv_bfloat16* __restrict__ Alo,
                 const __nv_bfloat16* __restrict__ Bhi, const __nv_bfloat16* __restrict__ Blo,
                 float* __restrict__ C, int K, int Ntot)
{
    extern __shared__ __align__(1024) char smem[];
    const uint32_t sbase = smem_u32(smem);
    const int tid  = threadIdx.x;
    const int wid  = tid >> 5;
    const int lane = tid & 31;
    const int m0 = blockIdx.y * BM;
    const int n0 = blockIdx.x * BN;

    const int wm = wid & 1;          // 0..1 -> 64-row half
    const int wn = wid >> 1;         // 0..3 -> 32-col slice
    const int m_off = wm * 64;
    const int n_off = wn * 32;

    const __nv_bfloat16* aS[2] = { Ahi + (size_t)m0 * K, Alo + (size_t)m0 * K };
    const __nv_bfloat16* bS[2] = { Bhi + (size_t)n0 * K, Blo + (size_t)n0 * K };

    const int NIT = K / BK;

    // per stage: each term is 512 16B chunks -> 2 per thread
    auto load_stage = [&](int sbuf, int k0) {
        uint32_t stg = sbase + sbuf * STAGE_B;
#pragma unroll
        for (int p = 0; p < 2; p++) {
            uint32_t part = stg + p * A_BYTES;
            const __nv_bfloat16* src = aS[p] + k0;
#pragma unroll
            for (int r = 0; r < 2; r++) {
                int idx = r * 256 + tid;
                int row = idx >> 2, c = idx & 3;
                uint32_t soff = SWZ64((uint32_t)(row * 64 + c * 16));
                CP_ASYNC16(part + soff, src + (size_t)row * K + c * 8);
            }
        }
#pragma unroll
        for (int p = 0; p < 2; p++) {
            uint32_t part = stg + 2 * A_BYTES + p * B_BYTES;
            const __nv_bfloat16* src = bS[p] + k0;
#pragma unroll
            for (int r = 0; r < 2; r++) {
                int idx = r * 256 + tid;
                int row = idx >> 2, c = idx & 3;
                uint32_t soff = SWZ64((uint32_t)(row * 64 + c * 16));
                CP_ASYNC16(part + soff, src + (size_t)row * K + c * 8);
            }
        }
    };

    float c[4][4][4];
#pragma unroll
    for (int i = 0; i < 4; i++)
#pragma unroll
        for (int j = 0; j < 4; j++)
#pragma unroll
            for (int t = 0; t < 4; t++) c[i][j][t] = 0.f;

    // prologue: 2 stages in flight
    load_stage(0, 0); CP_COMMIT();
    load_stage(1, BK); CP_COMMIT();

    const int lr = lane & 15;
    const int lk = lane >> 4;

    int sbuf = 0;
    for (int it = 0; it < NIT; it++) {
        CP_WAIT(1);
        __syncthreads();
        if (it + 2 < NIT) { load_stage((sbuf + 2) % 3, (it + 2) * BK); CP_COMMIT(); }

        uint32_t stg  = sbase + sbuf * STAGE_B;
        uint32_t aHiB = stg;
        uint32_t aLoB = stg + A_BYTES;
        uint32_t bHiB = stg + 2 * A_BYTES;
        uint32_t bLoB = stg + 2 * A_BYTES + B_BYTES;

#pragma unroll
        for (int ks = 0; ks < 2; ks++) {
            // load B fragments for this warp's 32 cols (2 groups of 16)
            uint32_t bh[2][4], bl[2][4];
#pragma unroll
            for (int ng = 0; ng < 2; ng++) {
                uint32_t off = (uint32_t)((n_off + ng * 16 + lr) * 64 + ks * 32 + lk * 16);
                uint32_t sw = SWZ64(off);
                LDSM_X4(bh[ng][0], bh[ng][1], bh[ng][2], bh[ng][3], bHiB + sw);
                LDSM_X4(bl[ng][0], bl[ng][1], bl[ng][2], bl[ng][3], bLoB + sw);
            }
#pragma unroll
            for (int mi = 0; mi < 4; mi++) {
                uint32_t off = (uint32_t)((m_off + mi * 16 + lr) * 64 + ks * 32 + lk * 16);
                uint32_t sw = SWZ64(off);
                uint32_t ahi[4], alo[4];
                LDSM_X4(ahi[0], ahi[1], ahi[2], ahi[3], aHiB + sw);
                LDSM_X4(alo[0], alo[1], alo[2], alo[3], aLoB + sw);
#pragma unroll
                for (int ng = 0; ng < 2; ng++) {
                    MMA16816(c[mi][ng*2+0], ahi, bh[ng][0], bh[ng][2]);
                    MMA16816(c[mi][ng*2+1], ahi, bh[ng][1], bh[ng][3]);
                    MMA16816(c[mi][ng*2+0], alo, bh[ng][0], bh[ng][2]);
                    MMA16816(c[mi][ng*2+1], alo, bh[ng][1], bh[ng][3]);
                    MMA16816(c[mi][ng*2+0], ahi, bl[ng][0], bl[ng][2]);
                    MMA16816(c[mi][ng*2+1], ahi, bl[ng][1], bl[ng][3]);
                }
            }
        }
        sbuf = (sbuf + 1) % 3;
    }

    // epilogue
    const int cr = lane >> 2;
    const int cc = (lane & 3) * 2;
#pragma unroll
    for (int mi = 0; mi < 4; mi++) {
        int r0 = m0 + m_off + mi * 16 + cr;
#pragma unroll
        for (int j = 0; j < 4; j++) {
            int col = n0 + n_off + j * 8 + cc;
            float2 v0 = make_float2(c[mi][j][0], c[mi][j][1]);
            float2 v1 = make_float2(c[mi][j][2], c[mi][j][3]);
            *(float2*)(C + (size_t)r0 * Ntot + col)       = v0;
            *(float2*)(C + (size_t)(r0 + 8) * Ntot + col) = v1;
        }
    }
}

// ---------------------------------------------------------------------------
// Tensor-core flash attention with ALiBi + causal mask. (round-4 kernel)
// CTA: 128 queries x one (b,h); 8 warps x 16 query rows.
// ---------------------------------------------------------------------------
#define ATT_SMEM 131072
#define Q_HI 0
#define Q_LO 16384
#define STG0 32768
#define P_HI 98304
#define P_LO 114688

__global__ __launch_bounds__(256, 1)
void attn_mma(const float* __restrict__ qkv,
              __nv_bfloat16* __restrict__ out_hi, __nv_bfloat16* __restrict__ out_lo)
{
    extern __shared__ __align__(1024) char smem[];
    const uint32_t sbase = smem_u32(smem);
    const int tid  = threadIdx.x;
    const int wid  = tid >> 5;
    const int lane = tid & 31;
    const int lr   = lane & 15;
    const int lk   = lane >> 4;

    const int qt = blockIdx.x;
    const int bh = blockIdx.y;
    const int b  = bh >> 4;
    const int h  = bh & 15;
    const int q0 = qt * 128;

    const float slope = exp2f(-0.5f * (float)(h + 1));
    const float scale = 0.125f;

    const size_t rs = 3 * DIM;
    const float* qbase = qkv + (size_t)b * SEQ * rs + h * HD;
    const float* kbase = qbase + DIM;
    const float* vbase = qbase + 2 * DIM;

    // ---- load Q tile (128x64 fp32), scale, split hi/lo, store swizzled ----
#pragma unroll
    for (int r = 0; r < 8; r++) {
        int idx = r * 256 + tid;
        int row = idx >> 4;
        int c4  = idx & 15;
        float4 v = *(const float4*)(qbase + (size_t)(q0 + row) * rs + c4 * 4);
        v.x *= scale; v.y *= scale; v.z *= scale; v.w *= scale;
        __nv_bfloat16 hx = __float2bfloat16(v.x), hy = __float2bfloat16(v.y);
        __nv_bfloat16 hz = __float2bfloat16(v.z), hw = __float2bfloat16(v.w);
        uint32_t soff = SWZ128((uint32_t)(row * 128 + c4 * 8));
        uint2 hv, lv;
        hv.x = pack_bf2(v.x, v.y); hv.y = pack_bf2(v.z, v.w);
        lv.x = pack_bf2(v.x - __bfloat162float(hx), v.y - __bfloat162float(hy));
        lv.y = pack_bf2(v.z - __bfloat162float(hz), v.w - __bfloat162float(hw));
        *(uint2*)(smem + Q_HI + soff) = hv;
        *(uint2*)(smem + Q_LO + soff) = lv;
    }

    float4 kreg[4], vreg[4];
    const int pr_row = tid >> 2;
    const int pr_c4  = (tid & 3) * 4;

    auto load_kv = [&](int kt) {
        const float* kp = kbase + (size_t)(kt * 64 + pr_row) * rs + pr_c4 * 4;
        const float* vp = vbase + (size_t)(kt * 64 + pr_row) * rs + pr_c4 * 4;
#pragma unroll
        for (int i = 0; i < 4; i++) {
            kreg[i] = *(const float4*)(kp + i * 4);
            vreg[i] = *(const float4*)(vp + i * 4);
        }
    };

    float cs[8][4];
    float co[8][4];
#pragma unroll
    for (int j = 0; j < 8; j++)
#pragma unroll
        for (int t = 0; t < 4; t++) co[j][t] = 0.f;

    float m0v = -1e30f, m1v = -1e30f, l0v = 0.f, l1v = 0.f;

    const int r0 = lane >> 2;
    const int ccol = (lane & 3) * 2;
    const int gi0 = q0 + wid * 16 + r0;
    const int gi1 = gi0 + 8;

    const int nkt = 2 * qt + 2;
    load_kv(0);

    for (int kt = 0; kt < nkt; kt++) {
        const int s = kt & 1;
        const int k0 = kt * 64;
        uint32_t stg = sbase + STG0 + s * 32768;

#pragma unroll
        for (int i = 0; i < 4; i++) {
            uint32_t soff = SWZ128((uint32_t)(pr_row * 128 + (pr_c4 + i) * 8));
            float4 kv = kreg[i];
            __nv_bfloat16 ax = __float2bfloat16(kv.x), ay = __float2bfloat16(kv.y);
            __nv_bfloat16 az = __float2bfloat16(kv.z), aw = __float2bfloat16(kv.w);
            uint2 hv, lv;
            hv.x = pack_bf2(kv.x, kv.y); hv.y = pack_bf2(kv.z, kv.w);
            lv.x = pack_bf2(kv.x - __bfloat162float(ax), kv.y - __bfloat162float(ay));
            lv.y = pack_bf2(kv.z - __bfloat162float(az), kv.w - __bfloat162float(aw));
            *(uint2*)(smem + (stg - sbase) + 0    + soff) = hv;
            *(uint2*)(smem + (stg - sbase) + 8192 + soff) = lv;
            float4 vv = vreg[i];
            __nv_bfloat16 bx = __float2bfloat16(vv.x), by = __float2bfloat16(vv.y);
            __nv_bfloat16 bz = __float2bfloat16(vv.z), bw = __float2bfloat16(vv.w);
            uint2 hv2, lv2;
            hv2.x = pack_bf2(vv.x, vv.y); hv2.y = pack_bf2(vv.z, vv.w);
            lv2.x = pack_bf2(vv.x - __bfloat162float(bx), vv.y - __bfloat162float(by));
            lv2.y = pack_bf2(vv.z - __bfloat162float(bz), vv.w - __bfloat162float(bw));
            *(uint2*)(smem + (stg - sbase) + 16384 + soff) = hv2;
            *(uint2*)(smem + (stg - sbase) + 24576 + soff) = lv2;
        }
        __syncthreads();

        if (kt + 1 < nkt) load_kv(kt + 1);

        // ---- S = Q K^T (3-term) ----
#pragma unroll
        for (int j = 0; j < 8; j++)
#pragma unroll
            for (int t = 0; t < 4; t++) cs[j][t] = 0.f;

        uint32_t kHiB = stg, kLoB = stg + 8192;
#pragma unroll
        for (int ks = 0; ks < 4; ks++) {
            uint32_t qoff = SWZ128((uint32_t)((wid * 16 + lr) * 128 + ks * 32 + lk * 16));
            uint32_t ahi[4], alo[4];
            LDSM_X4(ahi[0], ahi[1], ahi[2], ahi[3], sbase + Q_HI + qoff);
            LDSM_X4(alo[0], alo[1], alo[2], alo[3], sbase + Q_LO + qoff);
#pragma unroll
            for (int ng = 0; ng < 4; ng++) {
                uint32_t boff = SWZ128((uint32_t)((ng * 16 + lr) * 128 + ks * 32 + lk * 16));
                uint32_t bh0, bh1, bh2, bh3, bl0, bl1, bl2, bl3;
                LDSM_X4(bh0, bh1, bh2, bh3, kHiB + boff);
                LDSM_X4(bl0, bl1, bl2, bl3, kLoB + boff);
                MMA16816(cs[ng*2+0], ahi, bh0, bh2);
                MMA16816(cs[ng*2+1], ahi, bh1, bh3);
                MMA16816(cs[ng*2+0], alo, bh0, bh2);
                MMA16816(cs[ng*2+1], alo, bh1, bh3);
                MMA16816(cs[ng*2+0], ahi, bl0, bl2);
                MMA16816(cs[ng*2+1], ahi, bl1, bl3);
            }
        }

        // ---- ALiBi + causal mask ----
#pragma unroll
        for (int nb = 0; nb < 8; nb++) {
#pragma unroll
            for (int c = 0; c < 2; c++) {
                int gj = k0 + nb * 8 + ccol + c;
                float rel0 = slope * (float)(gj - gi0);
                float rel1 = slope * (float)(gj - gi1);
                cs[nb][c]     = (gj > gi0) ? -1e30f : cs[nb][c]     - rel0;
                cs[nb][2 + c] = (gj > gi1) ? -1e30f : cs[nb][2 + c] - rel1;
            }
        }

        // ---- online softmax ----
        float mx0 = -1e30f, mx1 = -1e30f;
#pragma unroll
        for (int nb = 0; nb < 8; nb++) {
            mx0 = fmaxf(mx0, fmaxf(cs[nb][0], cs[nb][1]));
            mx1 = fmaxf(mx1, fmaxf(cs[nb][2], cs[nb][3]));
        }
        mx0 = fmaxf(mx0, __shfl_xor_sync(0xffffffff, mx0, 1));
        mx0 = fmaxf(mx0, __shfl_xor_sync(0xffffffff, mx0, 2));
        mx1 = fmaxf(mx1, __shfl_xor_sync(0xffffffff, mx1, 1));
        mx1 = fmaxf(mx1, __shfl_xor_sync(0xffffffff, mx1, 2));

        float mn0 = fmaxf(m0v, mx0), mn1 = fmaxf(m1v, mx1);
        float corr0 = __expf(m0v - mn0), corr1 = __expf(m1v - mn1);
        m0v = mn0; m1v = mn1;

        float sum0 = 0.f, sum1 = 0.f;
        const int prow0 = wid * 16 + r0;
#pragma unroll
        for (int nb = 0; nb < 8; nb++) {
            float p00 = __expf(cs[nb][0] - mn0);
            float p01 = __expf(cs[nb][1] - mn0);
            float p10 = __expf(cs[nb][2] - mn1);
            float p11 = __expf(cs[nb][3] - mn1);
            sum0 += p00 + p01;
            sum1 += p10 + p11;
            uint32_t off0 = SWZ128((uint32_t)(prow0 * 128 + nb * 16 + (lane & 3) * 4));
            uint32_t off1 = SWZ128((uint32_t)((prow0 + 8) * 128 + nb * 16 + (lane & 3) * 4));
            __nv_bfloat16 h00 = __float2bfloat16(p00), h01 = __float2bfloat16(p01);
            __nv_bfloat16 h10 = __float2bfloat16(p10), h11 = __float2bfloat16(p11);
            *(uint32_t*)(smem + P_HI + off0) = pack_bf2(p00, p01);
            *(uint32_t*)(smem + P_HI + off1) = pack_bf2(p10, p11);
            *(uint32_t*)(smem + P_LO + off0) =
                pack_bf2(p00 - __bfloat162float(h00), p01 - __bfloat162float(h01));
            *(uint32_t*)(smem + P_LO + off1) =
                pack_bf2(p10 - __bfloat162float(h10), p11 - __bfloat162float(h11));
        }
        sum0 += __shfl_xor_sync(0xffffffff, sum0, 1);
        sum0 += __shfl_xor_sync(0xffffffff, sum0, 2);
        sum1 += __shfl_xor_sync(0xffffffff, sum1, 1);
        sum1 += __shfl_xor_sync(0xffffffff, sum1, 2);
        l0v = l0v * corr0 + sum0;
        l1v = l1v * corr1 + sum1;

#pragma unroll
        for (int nb = 0; nb < 8; nb++) {
            co[nb][0] *= corr0; co[nb][1] *= corr0;
            co[nb][2] *= corr1; co[nb][3] *= corr1;
        }
        __syncwarp();

        // ---- O += P V (3-term; V via ldmatrix.trans) ----
        uint32_t vHiB = stg + 16384, vLoB = stg + 24576;
#pragma unroll
        for (int ks = 0; ks < 4; ks++) {
            uint32_t poff = SWZ128((uint32_t)((wid * 16 + lr) * 128 + ks * 32 + lk * 16));
            uint32_t phi[4], plo[4];
            LDSM_X4(phi[0], phi[1], phi[2], phi[3], sbase + P_HI + poff);
            LDSM_X4(plo[0], plo[1], plo[2], plo[3], sbase + P_LO + poff);
#pragma unroll
            for (int ng = 0; ng < 4; ng++) {
                uint32_t voff = SWZ128((uint32_t)((ks * 16 + lr) * 128 + ng * 32 + lk * 16));
                uint32_t vh0, vh1, vh2, vh3, vl0, vl1, vl2, vl3;
                LDSM_X4_T(vh0, vh1, vh2, vh3, vHiB + voff);
                LDSM_X4_T(vl0, vl1, vl2, vl3, vLoB + voff);
                MMA16816(co[ng*2+0], phi, vh0, vh1);
                MMA16816(co[ng*2+1], phi, vh2, vh3);
                MMA16816(co[ng*2+0], plo, vh0, vh1);
                MMA16816(co[ng*2+1], plo, vh2, vh3);
                MMA16816(co[ng*2+0], phi, vl0, vl1);
                MMA16816(co[ng*2+1], phi, vl2, vl3);
            }
        }
        __syncthreads();
    }

    // ---- normalize + write bf16 hi/lo directly ----
    float inv0 = 1.0f / l0v, inv1 = 1.0f / l1v;
    size_t row0 = (size_t)(b * SEQ + gi0) * DIM + h * HD;
    size_t row1 = (size_t)(b * SEQ + gi1) * DIM + h * HD;
#pragma unroll
    for (int nb = 0; nb < 8; nb++) {
        int d = nb * 8 + ccol;
        float o00 = co[nb][0] * inv0, o01 = co[nb][1] * inv0;
        float o10 = co[nb][2] * inv1, o11 = co[nb][3] * inv1;
        __nv_bfloat16 h00 = __float2bfloat16(o00), h01 = __float2bfloat16(o01);
        __nv_bfloat16 h10 = __float2bfloat16(o10), h11 = __float2bfloat16(o11);
        *(uint32_t*)(out_hi + row0 + d) = pack_bf2(o00, o01);
        *(uint32_t*)(out_hi + row1 + d) = pack_bf2(o10, o11);
        *(uint32_t*)(out_lo + row0 + d) =
            pack_bf2(o00 - __bfloat162float(h00), o01 - __bfloat162float(h01));
        *(uint32_t*)(out_lo + row1 + d) =
            pack_bf2(o10 - __bfloat162float(h10), o11 - __bfloat162float(h11));
    }
}

// ---------------------------------------------------------------------------
extern "C" void kernel_launch(void* const* d_in, const int* in_sizes, int n_in,
                              void* d_out, int out_size)
{
    const float* x    = (const float*)d_in[0];
    const float* Wqkv = (const float*)d_in[1];
    const float* Wo   = (const float*)d_in[2];
    float* out = (float*)d_out;

    float *qkv;
    __nv_bfloat16 *xhi, *xlo, *wqh, *wql, *woh, *wol, *ahi, *alo;
    cudaGetSymbolAddress((void**)&qkv,  g_qkv);
    cudaGetSymbolAddress((void**)&xhi,  g_xhi);
    cudaGetSymbolAddress((void**)&xlo,  g_xlo);
    cudaGetSymbolAddress((void**)&wqh,  g_wqh);
    cudaGetSymbolAddress((void**)&wql,  g_wql);
    cudaGetSymbolAddress((void**)&woh,  g_woh);
    cudaGetSymbolAddress((void**)&wol,  g_wol);
    cudaGetSymbolAddress((void**)&ahi,  g_ahi);
    cudaGetSymbolAddress((void**)&alo,  g_alo);

    cudaFuncSetAttribute(gemm_bf16x3, cudaFuncAttributeMaxDynamicSharedMemorySize, GEMM_SMEM);
    cudaFuncSetAttribute(attn_mma,    cudaFuncAttributeMaxDynamicSharedMemorySize, ATT_SMEM);

    // hi/lo splits of x and weights
    {
        int n4 = NTOK * DIM / 4;
        split_bf16<<<(n4 + 255) / 256, 256>>>(x, xhi, xlo, n4);
        n4 = 3 * DIM * DIM / 4;
        split_bf16<<<(n4 + 255) / 256, 256>>>(Wqkv, wqh, wql, n4);
        n4 = DIM * DIM / 4;
        split_bf16<<<(n4 + 255) / 256, 256>>>(Wo, woh, wol, n4);
    }

    // 1) qkv = x @ Wqkv^T
    {
        dim3 grid(3 * DIM / BN, NTOK / BM);   // (24, 32)
        gemm_bf16x3<<<grid, 256, GEMM_SMEM>>>(xhi, xlo, wqh, wql, qkv, DIM, 3 * DIM);
    }

    // 2) tensor-core flash attention (writes bf16 hi/lo directly)
    {
        dim3 grid(SEQ / 128, BATCH * HEADS);   // (16, 32)
        attn_mma<<<grid, 256, ATT_SMEM>>>(qkv, ahi, alo);
    }

    // 3) out = attn @ Wo^T
    {
        dim3 grid(DIM / BN, NTOK / BM);        // (8, 32)
        gemm_bf16x3<<<grid, 256, GEMM_SMEM>>>(ahi, alo, woh, wol, out, DIM, DIM);
    }
}